// round 15
// baseline (speedup 1.0000x reference)
#include <cuda_runtime.h>
#include <cuda_bf16.h>
#include <cstdint>

#define C      128
#define NTOT   16384
#define BATCH  16
#define KSB    272      // smem row stride bytes (128 bf16 + 8 pad)
#define WBUF   34816    // 128 * KSB
#define BPB    9        // blocks per batch
#define NTILE  128      // 128-px tiles per batch

__device__ float g_S[BATCH][8][16][16];
__device__ float g_Z[BATCH][C];
__device__ __nv_bfloat16 g_xT[BATCH][NTOT][C];   // pre-transposed bf16 x

// ---------------- primitives ----------------
__device__ __forceinline__ void mma_bf16(float d[4], const uint32_t a[4], uint32_t b0, uint32_t b1) {
    asm volatile(
        "mma.sync.aligned.m16n8k16.row.col.f32.bf16.bf16.f32 "
        "{%0,%1,%2,%3}, {%4,%5,%6,%7}, {%8,%9}, {%0,%1,%2,%3};"
        : "+f"(d[0]), "+f"(d[1]), "+f"(d[2]), "+f"(d[3])
        : "r"(a[0]), "r"(a[1]), "r"(a[2]), "r"(a[3]), "r"(b0), "r"(b1));
}
__device__ __forceinline__ void ldsm4(uint32_t r[4], uint32_t addr) {
    asm volatile("ldmatrix.sync.aligned.m8n8.x4.shared.b16 {%0,%1,%2,%3}, [%4];"
                 : "=r"(r[0]), "=r"(r[1]), "=r"(r[2]), "=r"(r[3]) : "r"(addr));
}
__device__ __forceinline__ uint32_t packbf(float lo, float hi) {
    __nv_bfloat162 h = __floats2bfloat162_rn(lo, hi);
    return *(uint32_t*)&h;
}
__device__ __forceinline__ void cpa16(uint32_t dst, const void* src) {
    asm volatile("cp.async.ca.shared.global [%0], [%1], 16;" :: "r"(dst), "l"(src));
}
__device__ __forceinline__ void cpa_commit() { asm volatile("cp.async.commit_group;" ::: "memory"); }
__device__ __forceinline__ void cpa_wait0()  { asm volatile("cp.async.wait_group 0;"  ::: "memory"); }

// one 128-px tile load from g_xT into smem buffer (512 threads, 4 chunks each)
__device__ __forceinline__ void load_tile_async(uint32_t sdst, const __nv_bfloat16* src_base, int t) {
#pragma unroll
    for (int i = 0; i < 4; i++) {
        int idx = i * 512 + t;
        int row = idx >> 4;
        int c16 = idx & 15;
        cpa16(sdst + (uint32_t)row * KSB + c16 * 16, (const char*)(src_base + row * C) + c16 * 16);
    }
}
// 128x128 f32 row-major -> bf16 smem (stride KSB), 512 threads
__device__ __forceinline__ void load_w(char* s, const float* __restrict__ W, int t) {
#pragma unroll
    for (int i = 0; i < 8; i++) {
        int idx = i * 512 + t;
        int mm = idx >> 5, k4 = (idx & 31) * 4;
        float4 v = *(const float4*)(W + mm * C + k4);
        *(uint2*)(s + mm * KSB + k4 * 2) = make_uint2(packbf(v.x, v.y), packbf(v.z, v.w));
    }
}

// 32x32 warp tile of a 128x128x128 GEMM; 16 warps (4x4). acc[2 mtiles][4 ntiles][4].
__device__ __forceinline__ void gemm_warp(uint32_t aA, uint32_t aB, float acc[2][4][4],
                                          int lane, int rm, int cn) {
    const int m = lane >> 3, lr = lane & 7;
    const uint32_t aA0 = aA + (uint32_t)(rm + (m & 1) * 8 + lr) * KSB + (m >> 1) * 16;
    const uint32_t aB0 = aB + (uint32_t)(cn + (m >> 1) * 8 + lr) * KSB + (m & 1) * 16;
#pragma unroll
    for (int kb = 0; kb < 8; kb++) {
        uint32_t a[2][4], b[2][4];
        ldsm4(a[0], aA0 + kb * 32);
        ldsm4(a[1], aA0 + 16 * KSB + kb * 32);
        ldsm4(b[0], aB0 + kb * 32);
        ldsm4(b[1], aB0 + 16 * KSB + kb * 32);
#pragma unroll
        for (int mt = 0; mt < 2; mt++)
#pragma unroll
            for (int p = 0; p < 2; p++) {
                mma_bf16(acc[mt][2 * p],     a[mt], b[p][0], b[p][1]);
                mma_bf16(acc[mt][2 * p + 1], a[mt], b[p][2], b[p][3]);
            }
    }
}

// ---- vectorized smem-free pre-transpose: x [b][c][n] f32 -> g_xT [b][n][c] bf16 ----
// Thread owns 4 consecutive pixels; per 8-channel chunk: 8 coalesced LDG.128 + 4 STG.128.
__global__ void __launch_bounds__(256)
transp_kernel(const float* __restrict__ x) {
    const int t = threadIdx.x;
    const int b = blockIdx.y;
    const int n0 = (blockIdx.x * 256 + t) * 4;
    if (blockIdx.x == 0) {                        // fold zero_kernel
        for (int i = t; i < 2048; i += 256) (&g_S[b][0][0][0])[i] = 0.f;
        if (t < 128) g_Z[b][t] = 0.f;
    }
    const float* xg = x + (size_t)b * C * NTOT + n0;
#pragma unroll
    for (int i = 0; i < 16; i++) {
        float4 r[8];
#pragma unroll
        for (int j = 0; j < 8; j++)
            r[j] = *(const float4*)(xg + (size_t)(i * 8 + j) * NTOT);
        const float* rp = (const float*)r;   // rp[j*4 + p] = channel i*8+j, pixel n0+p
#pragma unroll
        for (int p = 0; p < 4; p++) {
            uint4 o;
            o.x = packbf(rp[0 * 4 + p],  rp[1 * 4 + p]);
            o.y = packbf(rp[2 * 4 + p],  rp[3 * 4 + p]);
            o.z = packbf(rp[4 * 4 + p],  rp[5 * 4 + p]);
            o.w = packbf(rp[6 * 4 + p],  rp[7 * 4 + p]);
            *(uint4*)((char*)&g_xT[b][n0 + p][i * 8]) = o;
        }
    }
}

// ================= Pass A =================
__global__ void __launch_bounds__(512, 1)
passA_kernel(const float* __restrict__ Wk, const float* __restrict__ bk,
             const float* __restrict__ Wv, const float* __restrict__ bv) {
    extern __shared__ char sm[];
    char* sWk = sm;
    char* sWv = sm + WBUF;
    char* sV  = sm + 2 * WBUF;
    const uint32_t aWk = (uint32_t)__cvta_generic_to_shared(sWk);
    const uint32_t aWv = (uint32_t)__cvta_generic_to_shared(sWv);
    const uint32_t aV  = (uint32_t)__cvta_generic_to_shared(sV);
    const uint32_t aX[2] = {(uint32_t)__cvta_generic_to_shared(sm + 3 * WBUF),
                            (uint32_t)__cvta_generic_to_shared(sm + 4 * WBUF)};

    const int t = threadIdx.x, l = t & 31, w = t >> 5;
    const int g = l >> 2, tig = l & 3, m = l >> 3, lr = l & 7;
    const int rm = (w & 3) * 32, cn = (w >> 2) * 32;
    const int b = blockIdx.y;
    const __nv_bfloat16* xTb = &g_xT[b][0][0];

    load_w(sWk, Wk, t);
    load_w(sWv, Wv, t);
    int tt = blockIdx.x;
    load_tile_async(aX[0], xTb + tt * 128 * C, t);
    cpa_commit();

    float bk0[2], bk1[2], bv0[2], bv1[2];
#pragma unroll
    for (int mt = 0; mt < 2; mt++) {
        bk0[mt] = bk[rm + mt * 16 + g];     bk1[mt] = bk[rm + mt * 16 + 8 + g];
        bv0[mt] = bv[rm + mt * 16 + g];     bv1[mt] = bv[rm + mt * 16 + 8 + g];
    }

    float accS[2][2][4];
    float zacc[2][2] = {{0.f, 0.f}, {0.f, 0.f}};
#pragma unroll
    for (int mt = 0; mt < 2; mt++)
#pragma unroll
        for (int p = 0; p < 2; p++)
#pragma unroll
            for (int j = 0; j < 4; j++) accS[mt][p][j] = 0.f;

    const int h0 = rm >> 4;
    int cur = 0;
    for (; tt < NTILE; tt += BPB) {
        const int nxt = tt + BPB;
        cpa_wait0();
        __syncthreads();               // x(cur) ready; prior S-MMA reads of sV done
        if (nxt < NTILE) {
            load_tile_async(aX[cur ^ 1], xTb + nxt * 128 * C, t);
            cpa_commit();
        }

        float acc[2][4][4];
        // values GEMM
#pragma unroll
        for (int mt = 0; mt < 2; mt++)
#pragma unroll
            for (int nt = 0; nt < 4; nt++)
#pragma unroll
                for (int j = 0; j < 4; j++) acc[mt][nt][j] = 0.f;
        gemm_warp(aWv, aX[cur], acc, l, rm, cn);

        // scatter V+bv -> sV [v][n]
#pragma unroll
        for (int mt = 0; mt < 2; mt++) {
            const int r0 = rm + mt * 16 + g;
#pragma unroll
            for (int nt = 0; nt < 4; nt++) {
                const int n0 = cn + nt * 8 + tig * 2;
                *(uint32_t*)(sV + r0 * KSB + n0 * 2)       = packbf(acc[mt][nt][0] + bv0[mt], acc[mt][nt][1] + bv0[mt]);
                *(uint32_t*)(sV + (r0 + 8) * KSB + n0 * 2) = packbf(acc[mt][nt][2] + bv1[mt], acc[mt][nt][3] + bv1[mt]);
            }
        }

        // keys GEMM — independent of sV; hides the scatter before the sync
#pragma unroll
        for (int mt = 0; mt < 2; mt++)
#pragma unroll
            for (int nt = 0; nt < 4; nt++)
#pragma unroll
                for (int j = 0; j < 4; j++) acc[mt][nt][j] = 0.f;
        gemm_warp(aWk, aX[cur], acc, l, rm, cn);
        __syncthreads();               // sV complete from all warps

        // exp -> A fragments -> S-MMA (registers only)
#pragma unroll
        for (int kc = 0; kc < 2; kc++) {
#pragma unroll
            for (int mt = 0; mt < 2; mt++) {
                float e00 = __expf(acc[mt][2 * kc][0] + bk0[mt]);
                float e01 = __expf(acc[mt][2 * kc][1] + bk0[mt]);
                float e10 = __expf(acc[mt][2 * kc][2] + bk1[mt]);
                float e11 = __expf(acc[mt][2 * kc][3] + bk1[mt]);
                float e20 = __expf(acc[mt][2 * kc + 1][0] + bk0[mt]);
                float e21 = __expf(acc[mt][2 * kc + 1][1] + bk0[mt]);
                float e30 = __expf(acc[mt][2 * kc + 1][2] + bk1[mt]);
                float e31 = __expf(acc[mt][2 * kc + 1][3] + bk1[mt]);
                zacc[mt][0] += (e00 + e01) + (e20 + e21);
                zacc[mt][1] += (e10 + e11) + (e30 + e31);
                uint32_t ef[4];
                ef[0] = packbf(e00, e01);
                ef[1] = packbf(e10, e11);
                ef[2] = packbf(e20, e21);
                ef[3] = packbf(e30, e31);
                uint32_t bS[4];
                ldsm4(bS, aV + (uint32_t)((h0 + mt) * 16 + (m >> 1) * 8 + lr) * KSB
                             + (m & 1) * 16 + (cn + kc * 16) * 2);
                mma_bf16(accS[mt][0], ef, bS[0], bS[1]);
                mma_bf16(accS[mt][1], ef, bS[2], bS[3]);
            }
        }
        cur ^= 1;
    }

    // flush S and Z
#pragma unroll
    for (int mt = 0; mt < 2; mt++) {
        const int h = h0 + mt;
#pragma unroll
        for (int p = 0; p < 2; p++) {
            atomicAdd(&g_S[b][h][g][p * 8 + 2 * tig],         accS[mt][p][0]);
            atomicAdd(&g_S[b][h][g][p * 8 + 2 * tig + 1],     accS[mt][p][1]);
            atomicAdd(&g_S[b][h][g + 8][p * 8 + 2 * tig],     accS[mt][p][2]);
            atomicAdd(&g_S[b][h][g + 8][p * 8 + 2 * tig + 1], accS[mt][p][3]);
        }
    }
#pragma unroll
    for (int mt = 0; mt < 2; mt++)
#pragma unroll
        for (int half = 0; half < 2; half++) {
            float z = zacc[mt][half];
            z += __shfl_xor_sync(0xffffffffu, z, 1);
            z += __shfl_xor_sync(0xffffffffu, z, 2);
            if (tig == 0) atomicAdd(&g_Z[b][rm + mt * 16 + half * 8 + g], z);
        }
}

// ================= Pass B (computes G in prologue) =================
__global__ void __launch_bounds__(512, 1)
passB_kernel(const float* __restrict__ x, const float* __restrict__ Wq,
             const float* __restrict__ bq, const float* __restrict__ Wr,
             const float* __restrict__ br, float* __restrict__ out) {
    extern __shared__ char sm[];
    char* sWq = sm;
    char* sG  = sm + WBUF;
    char* sQ  = sm + 2 * WBUF;
    const uint32_t aWq = (uint32_t)__cvta_generic_to_shared(sWq);
    const uint32_t aG  = (uint32_t)__cvta_generic_to_shared(sG);
    const uint32_t aQ  = (uint32_t)__cvta_generic_to_shared(sQ);
    const uint32_t aX[2] = {(uint32_t)__cvta_generic_to_shared(sm + 3 * WBUF),
                            (uint32_t)__cvta_generic_to_shared(sm + 4 * WBUF)};

    const int t = threadIdx.x, l = t & 31, w = t >> 5;
    const int g = l >> 2, tig = l & 3;
    const int rm = (w & 3) * 32, cn = (w >> 2) * 32;
    const int b = blockIdx.y;
    const __nv_bfloat16* xTb = &g_xT[b][0][0];
    const float* xb = x + (size_t)b * C * NTOT;
    float* ob = out + (size_t)b * C * NTOT;

    load_w(sWq, Wq, t);
    int tt = blockIdx.x;
    load_tile_async(aX[0], xTb + tt * 128 * C, t);
    cpa_commit();

    // stage FULL S (2048 floats) + 1/Z in sQ (unused until first scatter)
    float* sSf = (float*)sQ;
    float* sZi = (float*)sQ + 2048;
    if (t < 128) sZi[t] = 1.0f / g_Z[b][t];
    for (int i = t; i < 2048; i += 512) sSf[i] = (&g_S[b][0][0][0])[i];
    __syncthreads();

    // G[c][hk] = (sum_v Wr[c][h*16+v] S[h][k][v]) / Z[hk] -> sG bf16
    {
        const int cc = t >> 2, q = t & 3;
#pragma unroll
        for (int h2 = 0; h2 < 2; h2++) {
            const int h = q * 2 + h2;
            float wr[16];
#pragma unroll
            for (int v4 = 0; v4 < 4; v4++) {
                float4 vv = *(const float4*)(Wr + cc * C + h * 16 + v4 * 4);
                wr[v4 * 4] = vv.x; wr[v4 * 4 + 1] = vv.y; wr[v4 * 4 + 2] = vv.z; wr[v4 * 4 + 3] = vv.w;
            }
            const float* Sh = sSf + h * 256;
#pragma unroll
            for (int k = 0; k < 16; k++) {
                float a0 = 0.f, a1 = 0.f, a2 = 0.f, a3 = 0.f;
#pragma unroll
                for (int v = 0; v < 16; v += 4) {
                    a0 += wr[v]     * Sh[k * 16 + v];
                    a1 += wr[v + 1] * Sh[k * 16 + v + 1];
                    a2 += wr[v + 2] * Sh[k * 16 + v + 2];
                    a3 += wr[v + 3] * Sh[k * 16 + v + 3];
                }
                const int hk = h * 16 + k;
                *(__nv_bfloat16*)(sG + cc * KSB + hk * 2) =
                    __float2bfloat16_rn(((a0 + a1) + (a2 + a3)) * sZi[hk]);
            }
        }
    }

    float bq0[2], bq1[2], br0[2], br1[2];
#pragma unroll
    for (int mt = 0; mt < 2; mt++) {
        bq0[mt] = bq[rm + mt * 16 + g];     bq1[mt] = bq[rm + mt * 16 + 8 + g];
        br0[mt] = br[rm + mt * 16 + g];     br1[mt] = br[rm + mt * 16 + 8 + g];
    }

    int cur = 0;
    for (; tt < NTILE; tt += BPB) {
        const int nxt = tt + BPB;
        cpa_wait0();
        __syncthreads();     // x(cur) ready; G/scratch done (iter0); prior GEMM2 sQ reads done
        if (nxt < NTILE) {
            load_tile_async(aX[cur ^ 1], xTb + nxt * 128 * C, t);
            cpa_commit();
        }

        float acc[2][4][4];
#pragma unroll
        for (int mt = 0; mt < 2; mt++)
#pragma unroll
            for (int nt = 0; nt < 4; nt++)
#pragma unroll
                for (int j = 0; j < 4; j++) acc[mt][nt][j] = 0.f;
        gemm_warp(aWq, aX[cur], acc, l, rm, cn);

        // exp in place
#pragma unroll
        for (int mt = 0; mt < 2; mt++)
#pragma unroll
            for (int nt = 0; nt < 4; nt++) {
                acc[mt][nt][0] = __expf(acc[mt][nt][0] + bq0[mt]);
                acc[mt][nt][1] = __expf(acc[mt][nt][1] + bq0[mt]);
                acc[mt][nt][2] = __expf(acc[mt][nt][2] + bq1[mt]);
                acc[mt][nt][3] = __expf(acc[mt][nt][3] + bq1[mt]);
            }

        // normalize (shfl over g-lanes) and scatter q -> dedicated sQ [n][kq]
#pragma unroll
        for (int mt = 0; mt < 2; mt++) {
            const int r0 = rm + mt * 16 + g;
#pragma unroll
            for (int nt = 0; nt < 4; nt++) {
                float s0 = acc[mt][nt][0] + acc[mt][nt][2];
                float s1 = acc[mt][nt][1] + acc[mt][nt][3];
                s0 += __shfl_xor_sync(0xffffffffu, s0, 4);
                s1 += __shfl_xor_sync(0xffffffffu, s1, 4);
                s0 += __shfl_xor_sync(0xffffffffu, s0, 8);
                s1 += __shfl_xor_sync(0xffffffffu, s1, 8);
                s0 += __shfl_xor_sync(0xffffffffu, s0, 16);
                s1 += __shfl_xor_sync(0xffffffffu, s1, 16);
                float i0 = 1.f / s0, i1 = 1.f / s1;
                const int n0 = cn + nt * 8 + tig * 2;
                *(__nv_bfloat16*)(sQ + n0 * KSB + r0 * 2)             = __float2bfloat16_rn(acc[mt][nt][0] * i0);
                *(__nv_bfloat16*)(sQ + n0 * KSB + (r0 + 8) * 2)       = __float2bfloat16_rn(acc[mt][nt][2] * i0);
                *(__nv_bfloat16*)(sQ + (n0 + 1) * KSB + r0 * 2)       = __float2bfloat16_rn(acc[mt][nt][1] * i1);
                *(__nv_bfloat16*)(sQ + (n0 + 1) * KSB + (r0 + 8) * 2) = __float2bfloat16_rn(acc[mt][nt][3] * i1);
            }
        }
        __syncthreads();     // sQ complete from all warps

        // out GEMM: D[c][n] = G[c][kq] * q[n][kq]
#pragma unroll
        for (int mt = 0; mt < 2; mt++)
#pragma unroll
            for (int nt = 0; nt < 4; nt++)
#pragma unroll
                for (int j = 0; j < 4; j++) acc[mt][nt][j] = 0.f;
        gemm_warp(aG, aQ, acc, l, rm, cn);

        // epilogue: out = D + br + x (f32 residual)
#pragma unroll
        for (int mt = 0; mt < 2; mt++) {
            const int r0 = rm + mt * 16 + g;
            const float* x0 = xb + (size_t)r0 * NTOT + tt * 128;
            const float* x1 = x0 + 8 * NTOT;
            float* o0 = ob + (size_t)r0 * NTOT + tt * 128;
            float* o1 = o0 + 8 * NTOT;
#pragma unroll
            for (int nt = 0; nt < 4; nt++) {
                const int n0 = cn + nt * 8 + tig * 2;
                float2 xa = *(const float2*)(x0 + n0);
                float2 xc = *(const float2*)(x1 + n0);
                *(float2*)(o0 + n0) = make_float2(acc[mt][nt][0] + br0[mt] + xa.x,
                                                  acc[mt][nt][1] + br0[mt] + xa.y);
                *(float2*)(o1 + n0) = make_float2(acc[mt][nt][2] + br1[mt] + xc.x,
                                                  acc[mt][nt][3] + br1[mt] + xc.y);
            }
        }
        cur ^= 1;
    }
}

extern "C" void kernel_launch(void* const* d_in, const int* in_sizes, int n_in,
                              void* d_out, int out_size) {
    const float* x  = (const float*)d_in[0];
    const float* Wk = (const float*)d_in[1];
    const float* bk = (const float*)d_in[2];
    const float* Wq = (const float*)d_in[3];
    const float* bq = (const float*)d_in[4];
    const float* Wv = (const float*)d_in[5];
    const float* bv = (const float*)d_in[6];
    const float* Wr = (const float*)d_in[7];
    const float* br = (const float*)d_in[8];
    float* out = (float*)d_out;

    const int smemA = 5 * WBUF;        // 174,080 B
    const int smemB = 5 * WBUF;        // 174,080 B
    cudaFuncSetAttribute(passA_kernel, cudaFuncAttributeMaxDynamicSharedMemorySize, smemA);
    cudaFuncSetAttribute(passB_kernel, cudaFuncAttributeMaxDynamicSharedMemorySize, smemB);

    transp_kernel<<<dim3(NTOT / 1024, BATCH), 256>>>(x);
    passA_kernel<<<dim3(BPB, BATCH), 512, smemA>>>(Wk, bk, Wv, bv);
    passB_kernel<<<dim3(BPB, BATCH), 512, smemB>>>(x, Wq, bq, Wr, br, out);
}

// round 16
// speedup vs baseline: 1.0153x; 1.0153x over previous
#include <cuda_runtime.h>
#include <cuda_bf16.h>
#include <cstdint>

#define C      128
#define NTOT   16384
#define BATCH  16
#define KSB    272      // smem row stride bytes (128 bf16 + 8 pad)
#define WBUF   34816    // 128 * KSB
#define BPB    9        // blocks per batch
#define NTILE  128      // 128-px tiles per batch

__device__ float g_S[BATCH][8][16][16];
__device__ float g_Z[BATCH][C];
__device__ __nv_bfloat16 g_xT[BATCH][NTOT][C];   // pre-transposed bf16 x

// ---------------- primitives ----------------
__device__ __forceinline__ void mma_bf16(float d[4], const uint32_t a[4], uint32_t b0, uint32_t b1) {
    asm volatile(
        "mma.sync.aligned.m16n8k16.row.col.f32.bf16.bf16.f32 "
        "{%0,%1,%2,%3}, {%4,%5,%6,%7}, {%8,%9}, {%0,%1,%2,%3};"
        : "+f"(d[0]), "+f"(d[1]), "+f"(d[2]), "+f"(d[3])
        : "r"(a[0]), "r"(a[1]), "r"(a[2]), "r"(a[3]), "r"(b0), "r"(b1));
}
__device__ __forceinline__ void ldsm4(uint32_t r[4], uint32_t addr) {
    asm volatile("ldmatrix.sync.aligned.m8n8.x4.shared.b16 {%0,%1,%2,%3}, [%4];"
                 : "=r"(r[0]), "=r"(r[1]), "=r"(r[2]), "=r"(r[3]) : "r"(addr));
}
__device__ __forceinline__ uint32_t packbf(float lo, float hi) {
    __nv_bfloat162 h = __floats2bfloat162_rn(lo, hi);
    return *(uint32_t*)&h;
}
__device__ __forceinline__ void cpa16(uint32_t dst, const void* src) {
    asm volatile("cp.async.ca.shared.global [%0], [%1], 16;" :: "r"(dst), "l"(src));
}
__device__ __forceinline__ void cpa_commit() { asm volatile("cp.async.commit_group;" ::: "memory"); }
__device__ __forceinline__ void cpa_wait0()  { asm volatile("cp.async.wait_group 0;"  ::: "memory"); }

// one 128-px tile load from g_xT into smem buffer (512 threads, 4 chunks each)
__device__ __forceinline__ void load_tile_async(uint32_t sdst, const __nv_bfloat16* src_base, int t) {
#pragma unroll
    for (int i = 0; i < 4; i++) {
        int idx = i * 512 + t;
        int row = idx >> 4;
        int c16 = idx & 15;
        cpa16(sdst + (uint32_t)row * KSB + c16 * 16, (const char*)(src_base + row * C) + c16 * 16);
    }
}
// 128x128 f32 row-major -> bf16 smem (stride KSB), 512 threads
__device__ __forceinline__ void load_w(char* s, const float* __restrict__ W, int t) {
#pragma unroll
    for (int i = 0; i < 8; i++) {
        int idx = i * 512 + t;
        int mm = idx >> 5, k4 = (idx & 31) * 4;
        float4 v = *(const float4*)(W + mm * C + k4);
        *(uint2*)(s + mm * KSB + k4 * 2) = make_uint2(packbf(v.x, v.y), packbf(v.z, v.w));
    }
}

// 32x32 warp tile of a 128x128x128 GEMM; 16 warps (4x4). acc[2 mtiles][4 ntiles][4].
__device__ __forceinline__ void gemm_warp(uint32_t aA, uint32_t aB, float acc[2][4][4],
                                          int lane, int rm, int cn) {
    const int m = lane >> 3, lr = lane & 7;
    const uint32_t aA0 = aA + (uint32_t)(rm + (m & 1) * 8 + lr) * KSB + (m >> 1) * 16;
    const uint32_t aB0 = aB + (uint32_t)(cn + (m >> 1) * 8 + lr) * KSB + (m & 1) * 16;
#pragma unroll
    for (int kb = 0; kb < 8; kb++) {
        uint32_t a[2][4], b[2][4];
        ldsm4(a[0], aA0 + kb * 32);
        ldsm4(a[1], aA0 + 16 * KSB + kb * 32);
        ldsm4(b[0], aB0 + kb * 32);
        ldsm4(b[1], aB0 + 16 * KSB + kb * 32);
#pragma unroll
        for (int mt = 0; mt < 2; mt++)
#pragma unroll
            for (int p = 0; p < 2; p++) {
                mma_bf16(acc[mt][2 * p],     a[mt], b[p][0], b[p][1]);
                mma_bf16(acc[mt][2 * p + 1], a[mt], b[p][2], b[p][3]);
            }
    }
}

// ---- vectorized pre-transpose, channel-split for occupancy ----
// grid (NTOT/1024, 4, BATCH): blockIdx.y = 32-channel segment.
// Thread owns 4 consecutive pixels x 32 channels: 32 coalesced LDG.128 + 16 STG.128.
__global__ void __launch_bounds__(256)
transp_kernel(const float* __restrict__ x) {
    const int t = threadIdx.x;
    const int cseg = blockIdx.y;                 // 0..3
    const int b = blockIdx.z;
    const int n0 = (blockIdx.x * 256 + t) * 4;
    if (blockIdx.x == 0 && cseg == 0) {          // fold zero_kernel
        for (int i = t; i < 2048; i += 256) (&g_S[0][0][0][0] + b * 2048)[i] = 0.f;
        if (t < 128) g_Z[b][t] = 0.f;
    }
    const float* xg = x + ((size_t)b * C + cseg * 32) * NTOT + n0;
#pragma unroll
    for (int i = 0; i < 4; i++) {                // 4 chunks of 8 channels
        float4 r[8];
#pragma unroll
        for (int j = 0; j < 8; j++)
            r[j] = *(const float4*)(xg + (size_t)(i * 8 + j) * NTOT);
        const float* rp = (const float*)r;       // rp[j*4+p] = channel chunk j, pixel n0+p
#pragma unroll
        for (int p = 0; p < 4; p++) {
            uint4 o;
            o.x = packbf(rp[0 * 4 + p], rp[1 * 4 + p]);
            o.y = packbf(rp[2 * 4 + p], rp[3 * 4 + p]);
            o.z = packbf(rp[4 * 4 + p], rp[5 * 4 + p]);
            o.w = packbf(rp[6 * 4 + p], rp[7 * 4 + p]);
            *(uint4*)((char*)&g_xT[b][n0 + p][cseg * 32 + i * 8]) = o;
        }
    }
}

// ================= Pass A =================
__global__ void __launch_bounds__(512, 1)
passA_kernel(const float* __restrict__ Wk, const float* __restrict__ bk,
             const float* __restrict__ Wv, const float* __restrict__ bv) {
    extern __shared__ char sm[];
    char* sWk = sm;
    char* sWv = sm + WBUF;
    char* sV  = sm + 2 * WBUF;
    const uint32_t aWk = (uint32_t)__cvta_generic_to_shared(sWk);
    const uint32_t aWv = (uint32_t)__cvta_generic_to_shared(sWv);
    const uint32_t aV  = (uint32_t)__cvta_generic_to_shared(sV);
    const uint32_t aX[2] = {(uint32_t)__cvta_generic_to_shared(sm + 3 * WBUF),
                            (uint32_t)__cvta_generic_to_shared(sm + 4 * WBUF)};

    const int t = threadIdx.x, l = t & 31, w = t >> 5;
    const int g = l >> 2, tig = l & 3, m = l >> 3, lr = l & 7;
    const int rm = (w & 3) * 32, cn = (w >> 2) * 32;
    const int b = blockIdx.y;
    const __nv_bfloat16* xTb = &g_xT[b][0][0];

    load_w(sWk, Wk, t);
    load_w(sWv, Wv, t);
    int tt = blockIdx.x;
    load_tile_async(aX[0], xTb + tt * 128 * C, t);
    cpa_commit();

    float bk0[2], bk1[2], bv0[2], bv1[2];
#pragma unroll
    for (int mt = 0; mt < 2; mt++) {
        bk0[mt] = bk[rm + mt * 16 + g];     bk1[mt] = bk[rm + mt * 16 + 8 + g];
        bv0[mt] = bv[rm + mt * 16 + g];     bv1[mt] = bv[rm + mt * 16 + 8 + g];
    }

    float accS[2][2][4];
    float zacc[2][2] = {{0.f, 0.f}, {0.f, 0.f}};
#pragma unroll
    for (int mt = 0; mt < 2; mt++)
#pragma unroll
        for (int p = 0; p < 2; p++)
#pragma unroll
            for (int j = 0; j < 4; j++) accS[mt][p][j] = 0.f;

    const int h0 = rm >> 4;
    int cur = 0;
    for (; tt < NTILE; tt += BPB) {
        const int nxt = tt + BPB;
        cpa_wait0();
        __syncthreads();               // x(cur) ready; prior S-MMA reads of sV done
        if (nxt < NTILE) {
            load_tile_async(aX[cur ^ 1], xTb + nxt * 128 * C, t);
            cpa_commit();
        }

        float acc[2][4][4];
        // values GEMM
#pragma unroll
        for (int mt = 0; mt < 2; mt++)
#pragma unroll
            for (int nt = 0; nt < 4; nt++)
#pragma unroll
                for (int j = 0; j < 4; j++) acc[mt][nt][j] = 0.f;
        gemm_warp(aWv, aX[cur], acc, l, rm, cn);

        // scatter V+bv -> sV [v][n]
#pragma unroll
        for (int mt = 0; mt < 2; mt++) {
            const int r0 = rm + mt * 16 + g;
#pragma unroll
            for (int nt = 0; nt < 4; nt++) {
                const int n0 = cn + nt * 8 + tig * 2;
                *(uint32_t*)(sV + r0 * KSB + n0 * 2)       = packbf(acc[mt][nt][0] + bv0[mt], acc[mt][nt][1] + bv0[mt]);
                *(uint32_t*)(sV + (r0 + 8) * KSB + n0 * 2) = packbf(acc[mt][nt][2] + bv1[mt], acc[mt][nt][3] + bv1[mt]);
            }
        }

        // keys GEMM — independent of sV; hides the scatter before the sync
#pragma unroll
        for (int mt = 0; mt < 2; mt++)
#pragma unroll
            for (int nt = 0; nt < 4; nt++)
#pragma unroll
                for (int j = 0; j < 4; j++) acc[mt][nt][j] = 0.f;
        gemm_warp(aWk, aX[cur], acc, l, rm, cn);
        __syncthreads();               // sV complete from all warps

        // exp -> A fragments -> S-MMA (registers only)
#pragma unroll
        for (int kc = 0; kc < 2; kc++) {
#pragma unroll
            for (int mt = 0; mt < 2; mt++) {
                float e00 = __expf(acc[mt][2 * kc][0] + bk0[mt]);
                float e01 = __expf(acc[mt][2 * kc][1] + bk0[mt]);
                float e10 = __expf(acc[mt][2 * kc][2] + bk1[mt]);
                float e11 = __expf(acc[mt][2 * kc][3] + bk1[mt]);
                float e20 = __expf(acc[mt][2 * kc + 1][0] + bk0[mt]);
                float e21 = __expf(acc[mt][2 * kc + 1][1] + bk0[mt]);
                float e30 = __expf(acc[mt][2 * kc + 1][2] + bk1[mt]);
                float e31 = __expf(acc[mt][2 * kc + 1][3] + bk1[mt]);
                zacc[mt][0] += (e00 + e01) + (e20 + e21);
                zacc[mt][1] += (e10 + e11) + (e30 + e31);
                uint32_t ef[4];
                ef[0] = packbf(e00, e01);
                ef[1] = packbf(e10, e11);
                ef[2] = packbf(e20, e21);
                ef[3] = packbf(e30, e31);
                uint32_t bS[4];
                ldsm4(bS, aV + (uint32_t)((h0 + mt) * 16 + (m >> 1) * 8 + lr) * KSB
                             + (m & 1) * 16 + (cn + kc * 16) * 2);
                mma_bf16(accS[mt][0], ef, bS[0], bS[1]);
                mma_bf16(accS[mt][1], ef, bS[2], bS[3]);
            }
        }
        cur ^= 1;
    }

    // flush S and Z
#pragma unroll
    for (int mt = 0; mt < 2; mt++) {
        const int h = h0 + mt;
#pragma unroll
        for (int p = 0; p < 2; p++) {
            atomicAdd(&g_S[b][h][g][p * 8 + 2 * tig],         accS[mt][p][0]);
            atomicAdd(&g_S[b][h][g][p * 8 + 2 * tig + 1],     accS[mt][p][1]);
            atomicAdd(&g_S[b][h][g + 8][p * 8 + 2 * tig],     accS[mt][p][2]);
            atomicAdd(&g_S[b][h][g + 8][p * 8 + 2 * tig + 1], accS[mt][p][3]);
        }
    }
#pragma unroll
    for (int mt = 0; mt < 2; mt++)
#pragma unroll
        for (int half = 0; half < 2; half++) {
            float z = zacc[mt][half];
            z += __shfl_xor_sync(0xffffffffu, z, 1);
            z += __shfl_xor_sync(0xffffffffu, z, 2);
            if (tig == 0) atomicAdd(&g_Z[b][rm + mt * 16 + half * 8 + g], z);
        }
}

// ================= Pass B (computes G in prologue) =================
__global__ void __launch_bounds__(512, 1)
passB_kernel(const float* __restrict__ x, const float* __restrict__ Wq,
             const float* __restrict__ bq, const float* __restrict__ Wr,
             const float* __restrict__ br, float* __restrict__ out) {
    extern __shared__ char sm[];
    char* sWq = sm;
    char* sG  = sm + WBUF;
    char* sQ  = sm + 2 * WBUF;
    const uint32_t aWq = (uint32_t)__cvta_generic_to_shared(sWq);
    const uint32_t aG  = (uint32_t)__cvta_generic_to_shared(sG);
    const uint32_t aQ  = (uint32_t)__cvta_generic_to_shared(sQ);
    const uint32_t aX[2] = {(uint32_t)__cvta_generic_to_shared(sm + 3 * WBUF),
                            (uint32_t)__cvta_generic_to_shared(sm + 4 * WBUF)};

    const int t = threadIdx.x, l = t & 31, w = t >> 5;
    const int g = l >> 2, tig = l & 3;
    const int rm = (w & 3) * 32, cn = (w >> 2) * 32;
    const int b = blockIdx.y;
    const __nv_bfloat16* xTb = &g_xT[b][0][0];
    const float* xb = x + (size_t)b * C * NTOT;
    float* ob = out + (size_t)b * C * NTOT;

    load_w(sWq, Wq, t);
    int tt = blockIdx.x;
    load_tile_async(aX[0], xTb + tt * 128 * C, t);
    cpa_commit();

    // stage FULL S (2048 floats) + 1/Z in sQ (unused until first scatter)
    float* sSf = (float*)sQ;
    float* sZi = (float*)sQ + 2048;
    if (t < 128) sZi[t] = 1.0f / g_Z[b][t];
    for (int i = t; i < 2048; i += 512) sSf[i] = (&g_S[b][0][0][0])[i];
    __syncthreads();

    // G[c][hk] = (sum_v Wr[c][h*16+v] S[h][k][v]) / Z[hk] -> sG bf16
    {
        const int cc = t >> 2, q = t & 3;
#pragma unroll
        for (int h2 = 0; h2 < 2; h2++) {
            const int h = q * 2 + h2;
            float wr[16];
#pragma unroll
            for (int v4 = 0; v4 < 4; v4++) {
                float4 vv = *(const float4*)(Wr + cc * C + h * 16 + v4 * 4);
                wr[v4 * 4] = vv.x; wr[v4 * 4 + 1] = vv.y; wr[v4 * 4 + 2] = vv.z; wr[v4 * 4 + 3] = vv.w;
            }
            const float* Sh = sSf + h * 256;
#pragma unroll
            for (int k = 0; k < 16; k++) {
                float a0 = 0.f, a1 = 0.f, a2 = 0.f, a3 = 0.f;
#pragma unroll
                for (int v = 0; v < 16; v += 4) {
                    a0 += wr[v]     * Sh[k * 16 + v];
                    a1 += wr[v + 1] * Sh[k * 16 + v + 1];
                    a2 += wr[v + 2] * Sh[k * 16 + v + 2];
                    a3 += wr[v + 3] * Sh[k * 16 + v + 3];
                }
                const int hk = h * 16 + k;
                *(__nv_bfloat16*)(sG + cc * KSB + hk * 2) =
                    __float2bfloat16_rn(((a0 + a1) + (a2 + a3)) * sZi[hk]);
            }
        }
    }

    float bq0[2], bq1[2], br0[2], br1[2];
#pragma unroll
    for (int mt = 0; mt < 2; mt++) {
        bq0[mt] = bq[rm + mt * 16 + g];     bq1[mt] = bq[rm + mt * 16 + 8 + g];
        br0[mt] = br[rm + mt * 16 + g];     br1[mt] = br[rm + mt * 16 + 8 + g];
    }

    int cur = 0;
    for (; tt < NTILE; tt += BPB) {
        const int nxt = tt + BPB;
        cpa_wait0();
        __syncthreads();     // x(cur) ready; G/scratch done (iter0); prior GEMM2 sQ reads done
        if (nxt < NTILE) {
            load_tile_async(aX[cur ^ 1], xTb + nxt * 128 * C, t);
            cpa_commit();
        }

        float acc[2][4][4];
#pragma unroll
        for (int mt = 0; mt < 2; mt++)
#pragma unroll
            for (int nt = 0; nt < 4; nt++)
#pragma unroll
                for (int j = 0; j < 4; j++) acc[mt][nt][j] = 0.f;
        gemm_warp(aWq, aX[cur], acc, l, rm, cn);

        // exp in place
#pragma unroll
        for (int mt = 0; mt < 2; mt++)
#pragma unroll
            for (int nt = 0; nt < 4; nt++) {
                acc[mt][nt][0] = __expf(acc[mt][nt][0] + bq0[mt]);
                acc[mt][nt][1] = __expf(acc[mt][nt][1] + bq0[mt]);
                acc[mt][nt][2] = __expf(acc[mt][nt][2] + bq1[mt]);
                acc[mt][nt][3] = __expf(acc[mt][nt][3] + bq1[mt]);
            }

        // normalize (shfl over g-lanes) and scatter q -> dedicated sQ [n][kq]
#pragma unroll
        for (int mt = 0; mt < 2; mt++) {
            const int r0 = rm + mt * 16 + g;
#pragma unroll
            for (int nt = 0; nt < 4; nt++) {
                float s0 = acc[mt][nt][0] + acc[mt][nt][2];
                float s1 = acc[mt][nt][1] + acc[mt][nt][3];
                s0 += __shfl_xor_sync(0xffffffffu, s0, 4);
                s1 += __shfl_xor_sync(0xffffffffu, s1, 4);
                s0 += __shfl_xor_sync(0xffffffffu, s0, 8);
                s1 += __shfl_xor_sync(0xffffffffu, s1, 8);
                s0 += __shfl_xor_sync(0xffffffffu, s0, 16);
                s1 += __shfl_xor_sync(0xffffffffu, s1, 16);
                float i0 = 1.f / s0, i1 = 1.f / s1;
                const int n0 = cn + nt * 8 + tig * 2;
                *(__nv_bfloat16*)(sQ + n0 * KSB + r0 * 2)             = __float2bfloat16_rn(acc[mt][nt][0] * i0);
                *(__nv_bfloat16*)(sQ + n0 * KSB + (r0 + 8) * 2)       = __float2bfloat16_rn(acc[mt][nt][2] * i0);
                *(__nv_bfloat16*)(sQ + (n0 + 1) * KSB + r0 * 2)       = __float2bfloat16_rn(acc[mt][nt][1] * i1);
                *(__nv_bfloat16*)(sQ + (n0 + 1) * KSB + (r0 + 8) * 2) = __float2bfloat16_rn(acc[mt][nt][3] * i1);
            }
        }
        __syncthreads();     // sQ complete from all warps

        // out GEMM: D[c][n] = G[c][kq] * q[n][kq]
#pragma unroll
        for (int mt = 0; mt < 2; mt++)
#pragma unroll
            for (int nt = 0; nt < 4; nt++)
#pragma unroll
                for (int j = 0; j < 4; j++) acc[mt][nt][j] = 0.f;
        gemm_warp(aG, aQ, acc, l, rm, cn);

        // epilogue: out = D + br + x (f32 residual)
#pragma unroll
        for (int mt = 0; mt < 2; mt++) {
            const int r0 = rm + mt * 16 + g;
            const float* x0 = xb + (size_t)r0 * NTOT + tt * 128;
            const float* x1 = x0 + 8 * NTOT;
            float* o0 = ob + (size_t)r0 * NTOT + tt * 128;
            float* o1 = o0 + 8 * NTOT;
#pragma unroll
            for (int nt = 0; nt < 4; nt++) {
                const int n0 = cn + nt * 8 + tig * 2;
                float2 xa = *(const float2*)(x0 + n0);
                float2 xc = *(const float2*)(x1 + n0);
                *(float2*)(o0 + n0) = make_float2(acc[mt][nt][0] + br0[mt] + xa.x,
                                                  acc[mt][nt][1] + br0[mt] + xa.y);
                *(float2*)(o1 + n0) = make_float2(acc[mt][nt][2] + br1[mt] + xc.x,
                                                  acc[mt][nt][3] + br1[mt] + xc.y);
            }
        }
        cur ^= 1;
    }
}

extern "C" void kernel_launch(void* const* d_in, const int* in_sizes, int n_in,
                              void* d_out, int out_size) {
    const float* x  = (const float*)d_in[0];
    const float* Wk = (const float*)d_in[1];
    const float* bk = (const float*)d_in[2];
    const float* Wq = (const float*)d_in[3];
    const float* bq = (const float*)d_in[4];
    const float* Wv = (const float*)d_in[5];
    const float* bv = (const float*)d_in[6];
    const float* Wr = (const float*)d_in[7];
    const float* br = (const float*)d_in[8];
    float* out = (float*)d_out;

    const int smemA = 5 * WBUF;        // 174,080 B
    const int smemB = 5 * WBUF;        // 174,080 B
    cudaFuncSetAttribute(passA_kernel, cudaFuncAttributeMaxDynamicSharedMemorySize, smemA);
    cudaFuncSetAttribute(passB_kernel, cudaFuncAttributeMaxDynamicSharedMemorySize, smemB);

    transp_kernel<<<dim3(NTOT / 1024, 4, BATCH), 256>>>(x);
    passA_kernel<<<dim3(BPB, BATCH), 512, smemA>>>(Wk, bk, Wv, bv);
    passB_kernel<<<dim3(BPB, BATCH), 512, smemB>>>(x, Wq, bq, Wr, br, out);
}

// round 17
// speedup vs baseline: 1.2548x; 1.2360x over previous
#include <cuda_runtime.h>
#include <cuda_bf16.h>
#include <cstdint>

#define C      128
#define NTOT   16384
#define BATCH  16
#define KSB    272      // smem row stride bytes (256B data + 16B pad)
#define WBUF   34816    // 128 * KSB
#define BPB    9        // blocks per batch
#define NTILE  128      // 128-px tiles per batch

__device__ float g_S[BATCH][8][16][16];
__device__ float g_Z[BATCH][C];
__device__ __nv_bfloat16 g_xB[(size_t)BATCH * C * NTOT];   // bf16 copy of x, SAME [b][c][n] layout

// ---------------- primitives ----------------
__device__ __forceinline__ void mma_bf16(float d[4], const uint32_t a[4], uint32_t b0, uint32_t b1) {
    asm volatile(
        "mma.sync.aligned.m16n8k16.row.col.f32.bf16.bf16.f32 "
        "{%0,%1,%2,%3}, {%4,%5,%6,%7}, {%8,%9}, {%0,%1,%2,%3};"
        : "+f"(d[0]), "+f"(d[1]), "+f"(d[2]), "+f"(d[3])
        : "r"(a[0]), "r"(a[1]), "r"(a[2]), "r"(a[3]), "r"(b0), "r"(b1));
}
__device__ __forceinline__ void ldsm4(uint32_t r[4], uint32_t addr) {
    asm volatile("ldmatrix.sync.aligned.m8n8.x4.shared.b16 {%0,%1,%2,%3}, [%4];"
                 : "=r"(r[0]), "=r"(r[1]), "=r"(r[2]), "=r"(r[3]) : "r"(addr));
}
__device__ __forceinline__ void ldsm4t(uint32_t r[4], uint32_t addr) {
    asm volatile("ldmatrix.sync.aligned.m8n8.x4.trans.shared.b16 {%0,%1,%2,%3}, [%4];"
                 : "=r"(r[0]), "=r"(r[1]), "=r"(r[2]), "=r"(r[3]) : "r"(addr));
}
__device__ __forceinline__ uint32_t packbf(float lo, float hi) {
    __nv_bfloat162 h = __floats2bfloat162_rn(lo, hi);
    return *(uint32_t*)&h;
}
__device__ __forceinline__ void cpa16(uint32_t dst, const void* src) {
    asm volatile("cp.async.ca.shared.global [%0], [%1], 16;" :: "r"(dst), "l"(src));
}
__device__ __forceinline__ void cpa_commit() { asm volatile("cp.async.commit_group;" ::: "memory"); }
__device__ __forceinline__ void cpa_wait0()  { asm volatile("cp.async.wait_group 0;"  ::: "memory"); }

// one 128-px tile (x [c][n] bf16) -> smem [c][n] rows (512 threads, 4 chunks each)
__device__ __forceinline__ void load_tile_async(uint32_t sdst, const __nv_bfloat16* src, int t) {
#pragma unroll
    for (int i = 0; i < 4; i++) {
        int idx = i * 512 + t;
        int row = idx >> 4;              // channel 0..127
        int c16 = idx & 15;              // 16B chunk within 256B row
        cpa16(sdst + (uint32_t)row * KSB + c16 * 16,
              (const char*)(src + (size_t)row * NTOT) + c16 * 16);
    }
}
// 128x128 f32 row-major -> bf16 smem (stride KSB), 512 threads
__device__ __forceinline__ void load_w(char* s, const float* __restrict__ W, int t) {
#pragma unroll
    for (int i = 0; i < 8; i++) {
        int idx = i * 512 + t;
        int mm = idx >> 5, k4 = (idx & 31) * 4;
        float4 v = *(const float4*)(W + mm * C + k4);
        *(uint2*)(s + mm * KSB + k4 * 2) = make_uint2(packbf(v.x, v.y), packbf(v.z, v.w));
    }
}

// 32x32 warp tile; A: [m][k] non-trans ldsm; B: [k][n] trans ldsm (R6-proven addressing).
__device__ __forceinline__ void gemm_warpT(uint32_t aA, uint32_t aB, float acc[2][4][4],
                                           int lane, int rm, int cn) {
    const int m = lane >> 3, lr = lane & 7;
    const uint32_t aA0 = aA + (uint32_t)(rm + (m & 1) * 8 + lr) * KSB + (m >> 1) * 16;
    const uint32_t aB0 = aB + (uint32_t)((m & 1) * 8 + lr) * KSB + (cn + (m >> 1) * 8) * 2;
#pragma unroll
    for (int kb = 0; kb < 8; kb++) {
        uint32_t a[2][4];
        ldsm4(a[0], aA0 + kb * 32);
        ldsm4(a[1], aA0 + 16 * KSB + kb * 32);
#pragma unroll
        for (int p = 0; p < 2; p++) {
            uint32_t b[4];
            ldsm4t(b, aB0 + (uint32_t)kb * 16 * KSB + p * 32);
            mma_bf16(acc[0][2 * p],     a[0], b[0], b[1]);
            mma_bf16(acc[0][2 * p + 1], a[0], b[2], b[3]);
            mma_bf16(acc[1][2 * p],     a[1], b[0], b[1]);
            mma_bf16(acc[1][2 * p + 1], a[1], b[2], b[3]);
        }
    }
}

// ---- pure f32->bf16 convert, layout-preserving (fully coalesced both ways) ----
__global__ void __launch_bounds__(256)
convert_kernel(const float* __restrict__ x) {
    const size_t i = ((size_t)blockIdx.x * 256 + threadIdx.x) * 8;
    if (blockIdx.x < BATCH) {           // fold zero_kernel
        const int b = blockIdx.x, t = threadIdx.x;
        for (int j = t; j < 2048; j += 256) (&g_S[b][0][0][0])[j] = 0.f;
        if (t < 128) g_Z[b][t] = 0.f;
    }
    float4 v0 = *(const float4*)(x + i);
    float4 v1 = *(const float4*)(x + i + 4);
    uint4 o;
    o.x = packbf(v0.x, v0.y); o.y = packbf(v0.z, v0.w);
    o.z = packbf(v1.x, v1.y); o.w = packbf(v1.z, v1.w);
    *(uint4*)((char*)g_xB + i * 2) = o;
}

// ================= Pass A =================
__global__ void __launch_bounds__(512, 1)
passA_kernel(const float* __restrict__ Wk, const float* __restrict__ bk,
             const float* __restrict__ Wv, const float* __restrict__ bv) {
    extern __shared__ char sm[];
    char* sWk = sm;
    char* sWv = sm + WBUF;
    char* sV  = sm + 2 * WBUF;
    const uint32_t aWk = (uint32_t)__cvta_generic_to_shared(sWk);
    const uint32_t aWv = (uint32_t)__cvta_generic_to_shared(sWv);
    const uint32_t aV  = (uint32_t)__cvta_generic_to_shared(sV);
    const uint32_t aX[2] = {(uint32_t)__cvta_generic_to_shared(sm + 3 * WBUF),
                            (uint32_t)__cvta_generic_to_shared(sm + 4 * WBUF)};

    const int t = threadIdx.x, l = t & 31, w = t >> 5;
    const int g = l >> 2, tig = l & 3, m = l >> 3, lr = l & 7;
    const int rm = (w & 3) * 32, cn = (w >> 2) * 32;
    const int b = blockIdx.y;
    const __nv_bfloat16* xBb = g_xB + (size_t)b * C * NTOT;

    load_w(sWk, Wk, t);
    load_w(sWv, Wv, t);
    int tt = blockIdx.x;
    load_tile_async(aX[0], xBb + tt * 128, t);
    cpa_commit();

    float bk0[2], bk1[2], bv0[2], bv1[2];
#pragma unroll
    for (int mt = 0; mt < 2; mt++) {
        bk0[mt] = bk[rm + mt * 16 + g];     bk1[mt] = bk[rm + mt * 16 + 8 + g];
        bv0[mt] = bv[rm + mt * 16 + g];     bv1[mt] = bv[rm + mt * 16 + 8 + g];
    }

    float accS[2][2][4];
    float zacc[2][2] = {{0.f, 0.f}, {0.f, 0.f}};
#pragma unroll
    for (int mt = 0; mt < 2; mt++)
#pragma unroll
        for (int p = 0; p < 2; p++)
#pragma unroll
            for (int j = 0; j < 4; j++) accS[mt][p][j] = 0.f;

    const int h0 = rm >> 4;
    int cur = 0;
    for (; tt < NTILE; tt += BPB) {
        const int nxt = tt + BPB;
        cpa_wait0();
        __syncthreads();               // x(cur) ready; prior S-MMA reads of sV done
        if (nxt < NTILE) {
            load_tile_async(aX[cur ^ 1], xBb + nxt * 128, t);
            cpa_commit();
        }

        float acc[2][4][4];
        // values GEMM
#pragma unroll
        for (int mt = 0; mt < 2; mt++)
#pragma unroll
            for (int nt = 0; nt < 4; nt++)
#pragma unroll
                for (int j = 0; j < 4; j++) acc[mt][nt][j] = 0.f;
        gemm_warpT(aWv, aX[cur], acc, l, rm, cn);

        // scatter V+bv -> sV [v][n]
#pragma unroll
        for (int mt = 0; mt < 2; mt++) {
            const int r0 = rm + mt * 16 + g;
#pragma unroll
            for (int nt = 0; nt < 4; nt++) {
                const int n0 = cn + nt * 8 + tig * 2;
                *(uint32_t*)(sV + r0 * KSB + n0 * 2)       = packbf(acc[mt][nt][0] + bv0[mt], acc[mt][nt][1] + bv0[mt]);
                *(uint32_t*)(sV + (r0 + 8) * KSB + n0 * 2) = packbf(acc[mt][nt][2] + bv1[mt], acc[mt][nt][3] + bv1[mt]);
            }
        }

        // keys GEMM — independent of sV; hides the scatter before the sync
#pragma unroll
        for (int mt = 0; mt < 2; mt++)
#pragma unroll
            for (int nt = 0; nt < 4; nt++)
#pragma unroll
                for (int j = 0; j < 4; j++) acc[mt][nt][j] = 0.f;
        gemm_warpT(aWk, aX[cur], acc, l, rm, cn);
        __syncthreads();               // sV complete from all warps

        // exp -> A fragments -> S-MMA (registers only); S-MMA B = sV [v][n], k=n: non-trans
#pragma unroll
        for (int kc = 0; kc < 2; kc++) {
#pragma unroll
            for (int mt = 0; mt < 2; mt++) {
                float e00 = __expf(acc[mt][2 * kc][0] + bk0[mt]);
                float e01 = __expf(acc[mt][2 * kc][1] + bk0[mt]);
                float e10 = __expf(acc[mt][2 * kc][2] + bk1[mt]);
                float e11 = __expf(acc[mt][2 * kc][3] + bk1[mt]);
                float e20 = __expf(acc[mt][2 * kc + 1][0] + bk0[mt]);
                float e21 = __expf(acc[mt][2 * kc + 1][1] + bk0[mt]);
                float e30 = __expf(acc[mt][2 * kc + 1][2] + bk1[mt]);
                float e31 = __expf(acc[mt][2 * kc + 1][3] + bk1[mt]);
                zacc[mt][0] += (e00 + e01) + (e20 + e21);
                zacc[mt][1] += (e10 + e11) + (e30 + e31);
                uint32_t ef[4];
                ef[0] = packbf(e00, e01);
                ef[1] = packbf(e10, e11);
                ef[2] = packbf(e20, e21);
                ef[3] = packbf(e30, e31);
                uint32_t bS[4];
                ldsm4(bS, aV + (uint32_t)((h0 + mt) * 16 + (m >> 1) * 8 + lr) * KSB
                             + (m & 1) * 16 + (cn + kc * 16) * 2);
                mma_bf16(accS[mt][0], ef, bS[0], bS[1]);
                mma_bf16(accS[mt][1], ef, bS[2], bS[3]);
            }
        }
        cur ^= 1;
    }

    // flush S and Z
#pragma unroll
    for (int mt = 0; mt < 2; mt++) {
        const int h = h0 + mt;
#pragma unroll
        for (int p = 0; p < 2; p++) {
            atomicAdd(&g_S[b][h][g][p * 8 + 2 * tig],         accS[mt][p][0]);
            atomicAdd(&g_S[b][h][g][p * 8 + 2 * tig + 1],     accS[mt][p][1]);
            atomicAdd(&g_S[b][h][g + 8][p * 8 + 2 * tig],     accS[mt][p][2]);
            atomicAdd(&g_S[b][h][g + 8][p * 8 + 2 * tig + 1], accS[mt][p][3]);
        }
    }
#pragma unroll
    for (int mt = 0; mt < 2; mt++)
#pragma unroll
        for (int half = 0; half < 2; half++) {
            float z = zacc[mt][half];
            z += __shfl_xor_sync(0xffffffffu, z, 1);
            z += __shfl_xor_sync(0xffffffffu, z, 2);
            if (tig == 0) atomicAdd(&g_Z[b][rm + mt * 16 + half * 8 + g], z);
        }
}

// ================= Pass B (computes G in prologue) =================
__global__ void __launch_bounds__(512, 1)
passB_kernel(const float* __restrict__ x, const float* __restrict__ Wq,
             const float* __restrict__ bq, const float* __restrict__ Wr,
             const float* __restrict__ br, float* __restrict__ out) {
    extern __shared__ char sm[];
    char* sWq = sm;
    char* sG  = sm + WBUF;
    char* sQ  = sm + 2 * WBUF;
    const uint32_t aWq = (uint32_t)__cvta_generic_to_shared(sWq);
    const uint32_t aG  = (uint32_t)__cvta_generic_to_shared(sG);
    const uint32_t aQ  = (uint32_t)__cvta_generic_to_shared(sQ);
    const uint32_t aX[2] = {(uint32_t)__cvta_generic_to_shared(sm + 3 * WBUF),
                            (uint32_t)__cvta_generic_to_shared(sm + 4 * WBUF)};

    const int t = threadIdx.x, l = t & 31, w = t >> 5;
    const int g = l >> 2, tig = l & 3;
    const int rm = (w & 3) * 32, cn = (w >> 2) * 32;
    const int b = blockIdx.y;
    const __nv_bfloat16* xBb = g_xB + (size_t)b * C * NTOT;
    const float* xb = x + (size_t)b * C * NTOT;
    float* ob = out + (size_t)b * C * NTOT;

    load_w(sWq, Wq, t);
    int tt = blockIdx.x;
    load_tile_async(aX[0], xBb + tt * 128, t);
    cpa_commit();

    // stage FULL S (2048 floats) + 1/Z in sQ (unused until first scatter)
    float* sSf = (float*)sQ;
    float* sZi = (float*)sQ + 2048;
    if (t < 128) sZi[t] = 1.0f / g_Z[b][t];
    for (int i = t; i < 2048; i += 512) sSf[i] = (&g_S[b][0][0][0])[i];
    __syncthreads();

    // G[c][hk] = (sum_v Wr[c][h*16+v] S[h][k][v]) / Z[hk] -> sG bf16
    {
        const int cc = t >> 2, q = t & 3;
#pragma unroll
        for (int h2 = 0; h2 < 2; h2++) {
            const int h = q * 2 + h2;
            float wr[16];
#pragma unroll
            for (int v4 = 0; v4 < 4; v4++) {
                float4 vv = *(const float4*)(Wr + cc * C + h * 16 + v4 * 4);
                wr[v4 * 4] = vv.x; wr[v4 * 4 + 1] = vv.y; wr[v4 * 4 + 2] = vv.z; wr[v4 * 4 + 3] = vv.w;
            }
            const float* Sh = sSf + h * 256;
#pragma unroll
            for (int k = 0; k < 16; k++) {
                float a0 = 0.f, a1 = 0.f, a2 = 0.f, a3 = 0.f;
#pragma unroll
                for (int v = 0; v < 16; v += 4) {
                    a0 += wr[v]     * Sh[k * 16 + v];
                    a1 += wr[v + 1] * Sh[k * 16 + v + 1];
                    a2 += wr[v + 2] * Sh[k * 16 + v + 2];
                    a3 += wr[v + 3] * Sh[k * 16 + v + 3];
                }
                const int hk = h * 16 + k;
                *(__nv_bfloat16*)(sG + cc * KSB + hk * 2) =
                    __float2bfloat16_rn(((a0 + a1) + (a2 + a3)) * sZi[hk]);
            }
        }
    }

    float bq0[2], bq1[2], br0[2], br1[2];
#pragma unroll
    for (int mt = 0; mt < 2; mt++) {
        bq0[mt] = bq[rm + mt * 16 + g];     bq1[mt] = bq[rm + mt * 16 + 8 + g];
        br0[mt] = br[rm + mt * 16 + g];     br1[mt] = br[rm + mt * 16 + 8 + g];
    }

    int cur = 0;
    for (; tt < NTILE; tt += BPB) {
        const int nxt = tt + BPB;
        cpa_wait0();
        __syncthreads();     // x(cur) ready; G/scratch done (iter0); prior GEMM2 sQ reads done
        if (nxt < NTILE) {
            load_tile_async(aX[cur ^ 1], xBb + nxt * 128, t);
            cpa_commit();
        }

        float acc[2][4][4];
#pragma unroll
        for (int mt = 0; mt < 2; mt++)
#pragma unroll
            for (int nt = 0; nt < 4; nt++)
#pragma unroll
                for (int j = 0; j < 4; j++) acc[mt][nt][j] = 0.f;
        gemm_warpT(aWq, aX[cur], acc, l, rm, cn);

        // exp in place
#pragma unroll
        for (int mt = 0; mt < 2; mt++)
#pragma unroll
            for (int nt = 0; nt < 4; nt++) {
                acc[mt][nt][0] = __expf(acc[mt][nt][0] + bq0[mt]);
                acc[mt][nt][1] = __expf(acc[mt][nt][1] + bq0[mt]);
                acc[mt][nt][2] = __expf(acc[mt][nt][2] + bq1[mt]);
                acc[mt][nt][3] = __expf(acc[mt][nt][3] + bq1[mt]);
            }

        // normalize (shfl over g-lanes) and scatter q -> sQ [kq][n] (u32 stores)
#pragma unroll
        for (int mt = 0; mt < 2; mt++) {
            const int r0 = rm + mt * 16 + g;
#pragma unroll
            for (int nt = 0; nt < 4; nt++) {
                float s0 = acc[mt][nt][0] + acc[mt][nt][2];
                float s1 = acc[mt][nt][1] + acc[mt][nt][3];
                s0 += __shfl_xor_sync(0xffffffffu, s0, 4);
                s1 += __shfl_xor_sync(0xffffffffu, s1, 4);
                s0 += __shfl_xor_sync(0xffffffffu, s0, 8);
                s1 += __shfl_xor_sync(0xffffffffu, s1, 8);
                s0 += __shfl_xor_sync(0xffffffffu, s0, 16);
                s1 += __shfl_xor_sync(0xffffffffu, s1, 16);
                float i0 = 1.f / s0, i1 = 1.f / s1;
                const int n0 = cn + nt * 8 + tig * 2;
                *(uint32_t*)(sQ + r0 * KSB + n0 * 2)       = packbf(acc[mt][nt][0] * i0, acc[mt][nt][1] * i1);
                *(uint32_t*)(sQ + (r0 + 8) * KSB + n0 * 2) = packbf(acc[mt][nt][2] * i0, acc[mt][nt][3] * i1);
            }
        }
        __syncthreads();     // sQ complete from all warps

        // out GEMM: D[c][n] = G[c][kq] * q[kq][n]  (B trans)
#pragma unroll
        for (int mt = 0; mt < 2; mt++)
#pragma unroll
            for (int nt = 0; nt < 4; nt++)
#pragma unroll
                for (int j = 0; j < 4; j++) acc[mt][nt][j] = 0.f;
        gemm_warpT(aG, aQ, acc, l, rm, cn);

        // epilogue: out = D + br + x (f32 residual)
#pragma unroll
        for (int mt = 0; mt < 2; mt++) {
            const int r0 = rm + mt * 16 + g;
            const float* x0 = xb + (size_t)r0 * NTOT + tt * 128;
            const float* x1 = x0 + 8 * NTOT;
            float* o0 = ob + (size_t)r0 * NTOT + tt * 128;
            float* o1 = o0 + 8 * NTOT;
#pragma unroll
            for (int nt = 0; nt < 4; nt++) {
                const int n0 = cn + nt * 8 + tig * 2;
                float2 xa = *(const float2*)(x0 + n0);
                float2 xc = *(const float2*)(x1 + n0);
                *(float2*)(o0 + n0) = make_float2(acc[mt][nt][0] + br0[mt] + xa.x,
                                                  acc[mt][nt][1] + br0[mt] + xa.y);
                *(float2*)(o1 + n0) = make_float2(acc[mt][nt][2] + br1[mt] + xc.x,
                                                  acc[mt][nt][3] + br1[mt] + xc.y);
            }
        }
        cur ^= 1;
    }
}

extern "C" void kernel_launch(void* const* d_in, const int* in_sizes, int n_in,
                              void* d_out, int out_size) {
    const float* x  = (const float*)d_in[0];
    const float* Wk = (const float*)d_in[1];
    const float* bk = (const float*)d_in[2];
    const float* Wq = (const float*)d_in[3];
    const float* bq = (const float*)d_in[4];
    const float* Wv = (const float*)d_in[5];
    const float* bv = (const float*)d_in[6];
    const float* Wr = (const float*)d_in[7];
    const float* br = (const float*)d_in[8];
    float* out = (float*)d_out;

    const int smemA = 5 * WBUF;        // 174,080 B
    const int smemB = 5 * WBUF;        // 174,080 B
    cudaFuncSetAttribute(passA_kernel, cudaFuncAttributeMaxDynamicSharedMemorySize, smemA);
    cudaFuncSetAttribute(passB_kernel, cudaFuncAttributeMaxDynamicSharedMemorySize, smemB);

    convert_kernel<<<(int)(((size_t)BATCH * C * NTOT) / (256 * 8)), 256>>>(x);
    passA_kernel<<<dim3(BPB, BATCH), 512, smemA>>>(Wk, bk, Wv, bv);
    passB_kernel<<<dim3(BPB, BATCH), 512, smemB>>>(x, Wq, bq, Wr, br, out);
}